// round 1
// baseline (speedup 1.0000x reference)
#include <cuda_runtime.h>
#include <math.h>

#define Bn   16
#define Ln   512
#define Cn   38
#define Dn   512
#define Hn   8
#define En   64
#define DFFn 2048
#define NLn  3
#define DRESn 128
#define Mn   (Bn*Ln)     /* 8192 */
#define BHn  (Bn*Hn)     /* 128  */

// ---------------- scratch (static device memory; no allocs allowed) ----------------
__device__ float g_emb  [Mn*Dn];
__device__ float g_h    [Mn*Dn];
__device__ float g_q    [Mn*Dn];
__device__ float g_k    [Mn*Dn];
__device__ float g_v    [Mn*Dn];
__device__ float g_attnv[Mn*Dn];
__device__ float g_tmp  [Mn*Dn];
__device__ float g_x1   [Mn*Dn];
__device__ float g_enc  [Mn*Dn];
__device__ float g_ff1  [Mn*DFFn];
__device__ float g_scores[33554432];   // BHn*Ln*Ln = 128*512*512
__device__ float g_xcat [Mn*128];
__device__ float g_kpadT[128*Dn];

// ---------------- conv1d lowering: im2col pack + kernel transpose ----------------
__global__ void pack_xcat(const float* __restrict__ x, float* __restrict__ xc) {
    int bl = blockIdx.x;                 // 0..8191
    int b = bl >> 9, l = bl & 511;
    int i = threadIdx.x;                 // 0..127 (padded K)
    float val = 0.f;
    if (i < Cn*3) {
        int c = i / 3, t = i - c*3;
        int ls = (l - 1 + t + Ln) & (Ln - 1);   // wrap pad
        val = x[((size_t)b*Ln + ls)*Cn + c];
    }
    xc[(size_t)bl*128 + i] = val;
}

__global__ void pack_kpadT(const float* __restrict__ kern, float* __restrict__ kp) {
    int i = blockIdx.x;                  // 0..127 (k index)
    int d = threadIdx.x;                 // 0..511
    float val = 0.f;
    if (i < Cn*3) val = kern[(size_t)d*(Cn*3) + i];
    kp[(size_t)i*Dn + d] = val;
}

// ---------------- generic GEMM: C[M,N] = A[M,K]@B[K,N] (+bias) (opt gelu) ----------------
// 128x128 tile, 256 threads, 8x8 per-thread quadrant micro-tile, TK=16.
__global__ __launch_bounds__(256, 2)
void gemm128(const float* __restrict__ A, int lda,
             const float* __restrict__ Bm, int ldb,
             const float* __restrict__ bias,
             float* __restrict__ C, int ldc,
             int K, int do_gelu)
{
    __shared__ float As[16][128];
    __shared__ float Bs[16][128];
    const int tid = threadIdx.x;
    const int tx = tid & 15, ty = tid >> 4;
    const int m0 = blockIdx.y * 128, n0 = blockIdx.x * 128;

    float acc[2][2][4][4];
#pragma unroll
    for (int a = 0; a < 2; a++)
#pragma unroll
        for (int b = 0; b < 2; b++)
#pragma unroll
            for (int i = 0; i < 4; i++)
#pragma unroll
                for (int j = 0; j < 4; j++) acc[a][b][i][j] = 0.f;

    for (int k0 = 0; k0 < K; k0 += 16) {
#pragma unroll
        for (int i = 0; i < 2; i++) {
            int fid = tid + i*256;                 // 0..511 float4s
            int row = fid >> 2, seg = fid & 3;     // A: 128 rows x 4 float4
            float4 va = *(const float4*)(A + (size_t)(m0+row)*lda + k0 + seg*4);
            As[seg*4+0][row] = va.x; As[seg*4+1][row] = va.y;
            As[seg*4+2][row] = va.z; As[seg*4+3][row] = va.w;
            int kl = fid >> 5, ns = fid & 31;      // B: 16 rows x 32 float4
            *(float4*)(&Bs[kl][ns*4]) =
                *(const float4*)(Bm + (size_t)(k0+kl)*ldb + n0 + ns*4);
        }
        __syncthreads();
#pragma unroll
        for (int kk = 0; kk < 16; kk++) {
            float4 a0 = *(const float4*)(&As[kk][ty*4]);
            float4 a1 = *(const float4*)(&As[kk][64 + ty*4]);
            float4 b0 = *(const float4*)(&Bs[kk][tx*4]);
            float4 b1 = *(const float4*)(&Bs[kk][64 + tx*4]);
            float av[2][4] = {{a0.x,a0.y,a0.z,a0.w},{a1.x,a1.y,a1.z,a1.w}};
            float bv[2][4] = {{b0.x,b0.y,b0.z,b0.w},{b1.x,b1.y,b1.z,b1.w}};
#pragma unroll
            for (int rq = 0; rq < 2; rq++)
#pragma unroll
                for (int cq = 0; cq < 2; cq++)
#pragma unroll
                    for (int i2 = 0; i2 < 4; i2++)
#pragma unroll
                        for (int j = 0; j < 4; j++)
                            acc[rq][cq][i2][j] += av[rq][i2] * bv[cq][j];
        }
        __syncthreads();
    }

#pragma unroll
    for (int rq = 0; rq < 2; rq++)
#pragma unroll
        for (int cq = 0; cq < 2; cq++)
#pragma unroll
            for (int i2 = 0; i2 < 4; i2++) {
                int r = m0 + rq*64 + ty*4 + i2;
#pragma unroll
                for (int j = 0; j < 4; j++) {
                    int c = n0 + cq*64 + tx*4 + j;
                    float vv = acc[rq][cq][i2][j];
                    if (bias) vv += bias[c];
                    if (do_gelu) vv = 0.5f*vv*(1.0f + erff(vv*0.70710678118654752f));
                    C[(size_t)r*ldc + c] = vv;
                }
            }
}

// ---------------- attention scores: S[z,l,s] = scale * sum_e Q[b,l,h,e] K[b,s,h,e] ----------------
// batched NT gemm, 64x64 tiles, K=64
__global__ __launch_bounds__(256)
void attn_scores(const float* __restrict__ q, const float* __restrict__ kmat,
                 float* __restrict__ sc)
{
    const int z = blockIdx.z, b = z >> 3, h = z & 7;
    const float* A  = q    + (size_t)b*Ln*Dn + h*En;
    const float* Bm = kmat + (size_t)b*Ln*Dn + h*En;
    float* C = sc + (size_t)z*Ln*Ln;
    const int tid = threadIdx.x, tx = tid & 15, ty = tid >> 4;
    const int m0 = blockIdx.y*64, n0 = blockIdx.x*64;
    __shared__ float As[16][64];
    __shared__ float Bs[16][64];
    float acc[4][4] = {};
    for (int k0 = 0; k0 < En; k0 += 16) {
        int row = tid >> 2, seg = tid & 3;
        float4 va = *(const float4*)(A  + (size_t)(m0+row)*Dn + k0 + seg*4);
        As[seg*4+0][row]=va.x; As[seg*4+1][row]=va.y; As[seg*4+2][row]=va.z; As[seg*4+3][row]=va.w;
        float4 vb = *(const float4*)(Bm + (size_t)(n0+row)*Dn + k0 + seg*4);
        Bs[seg*4+0][row]=vb.x; Bs[seg*4+1][row]=vb.y; Bs[seg*4+2][row]=vb.z; Bs[seg*4+3][row]=vb.w;
        __syncthreads();
#pragma unroll
        for (int kk = 0; kk < 16; kk++) {
            float4 a = *(const float4*)(&As[kk][ty*4]);
            float4 bb= *(const float4*)(&Bs[kk][tx*4]);
            float av[4]={a.x,a.y,a.z,a.w}, bv[4]={bb.x,bb.y,bb.z,bb.w};
#pragma unroll
            for (int i=0;i<4;i++)
#pragma unroll
                for (int j=0;j<4;j++) acc[i][j] += av[i]*bv[j];
        }
        __syncthreads();
    }
#pragma unroll
    for (int i=0;i<4;i++)
#pragma unroll
        for (int j=0;j<4;j++)
            C[(size_t)(m0+ty*4+i)*Ln + n0+tx*4+j] = acc[i][j]*0.125f;  // 1/sqrt(64)
}

// ---------------- attention output: O[b,l,h*64+e] = sum_s S[z,l,s] V[b,s,h*64+e] ----------------
__global__ __launch_bounds__(256)
void attn_out(const float* __restrict__ sc, const float* __restrict__ v,
              float* __restrict__ o)
{
    const int z = blockIdx.z, b = z >> 3, h = z & 7;
    const float* A  = sc + (size_t)z*Ln*Ln;
    const float* Bv = v  + (size_t)b*Ln*Dn + h*En;
    float* C = o + (size_t)b*Ln*Dn + h*En;
    const int tid = threadIdx.x, tx = tid & 15, ty = tid >> 4;
    const int m0 = blockIdx.y*64;
    __shared__ float As[16][64];
    __shared__ float Bs[16][64];
    float acc[4][4] = {};
    for (int k0 = 0; k0 < Ln; k0 += 16) {
        int row = tid >> 2, seg = tid & 3;
        float4 va = *(const float4*)(A + (size_t)(m0+row)*Ln + k0 + seg*4);
        As[seg*4+0][row]=va.x; As[seg*4+1][row]=va.y; As[seg*4+2][row]=va.z; As[seg*4+3][row]=va.w;
        int kl = tid >> 4, ns = tid & 15;
        *(float4*)(&Bs[kl][ns*4]) = *(const float4*)(Bv + (size_t)(k0+kl)*Dn + ns*4);
        __syncthreads();
#pragma unroll
        for (int kk = 0; kk < 16; kk++) {
            float4 a = *(const float4*)(&As[kk][ty*4]);
            float4 bb= *(const float4*)(&Bs[kk][tx*4]);
            float av[4]={a.x,a.y,a.z,a.w}, bv[4]={bb.x,bb.y,bb.z,bb.w};
#pragma unroll
            for (int i=0;i<4;i++)
#pragma unroll
                for (int j=0;j<4;j++) acc[i][j] += av[i]*bv[j];
        }
        __syncthreads();
    }
#pragma unroll
    for (int i=0;i<4;i++)
#pragma unroll
        for (int j=0;j<4;j++)
            C[(size_t)(m0+ty*4+i)*Dn + tx*4+j] = acc[i][j];
}

// ---------------- softmax over rows of 512 ----------------
__global__ void softmax512(float* __restrict__ s) {
    size_t row = blockIdx.x;
    float* p = s + row*512;
    int t = threadIdx.x;                  // 256
    float a = p[t], b = p[t+256];
    float m = fmaxf(a, b);
#pragma unroll
    for (int o = 16; o > 0; o >>= 1) m = fmaxf(m, __shfl_xor_sync(0xFFFFFFFFu, m, o));
    __shared__ float sm[8], ss[8];
    if ((t & 31) == 0) sm[t >> 5] = m;
    __syncthreads();
    float M = fmaxf(fmaxf(fmaxf(sm[0],sm[1]),fmaxf(sm[2],sm[3])),
                    fmaxf(fmaxf(sm[4],sm[5]),fmaxf(sm[6],sm[7])));
    float e0 = __expf(a - M), e1 = __expf(b - M);
    float su = e0 + e1;
#pragma unroll
    for (int o = 16; o > 0; o >>= 1) su += __shfl_xor_sync(0xFFFFFFFFu, su, o);
    if ((t & 31) == 0) ss[t >> 5] = su;
    __syncthreads();
    float S = ss[0]+ss[1]+ss[2]+ss[3]+ss[4]+ss[5]+ss[6]+ss[7];
    float inv = 1.0f / S;
    p[t] = e0 * inv;
    p[t+256] = e1 * inv;
}

// ---------------- (optional residual add) + LayerNorm over rows of 512 ----------------
__global__ void add_ln512(const float* __restrict__ a, const float* __restrict__ b,
                          const float* __restrict__ g, const float* __restrict__ be,
                          float* __restrict__ o)
{
    int row = blockIdx.x, t = threadIdx.x;     // 256 threads, 2 elems each
    size_t base = (size_t)row * Dn;
    float v0 = a[base + t], v1 = a[base + t + 256];
    if (b) { v0 += b[base + t]; v1 += b[base + t + 256]; }
    float s = v0 + v1;
#pragma unroll
    for (int oo = 16; oo > 0; oo >>= 1) s += __shfl_xor_sync(0xFFFFFFFFu, s, oo);
    __shared__ float s1[8], s2[8];
    if ((t & 31) == 0) s1[t >> 5] = s;
    __syncthreads();
    float mean = (s1[0]+s1[1]+s1[2]+s1[3]+s1[4]+s1[5]+s1[6]+s1[7]) * (1.0f/Dn);
    float d0 = v0 - mean, d1 = v1 - mean;
    float q2 = d0*d0 + d1*d1;
#pragma unroll
    for (int oo = 16; oo > 0; oo >>= 1) q2 += __shfl_xor_sync(0xFFFFFFFFu, q2, oo);
    if ((t & 31) == 0) s2[t >> 5] = q2;
    __syncthreads();
    float var = (s2[0]+s2[1]+s2[2]+s2[3]+s2[4]+s2[5]+s2[6]+s2[7]) * (1.0f/Dn);
    float r = rsqrtf(var + 1e-5f);
    o[base + t]       = d0*r*g[t]     + be[t];
    o[base + t + 256] = d1*r*g[t+256] + be[t+256];
}

// ---------------- output copies ----------------
__global__ void copy_res(const float* __restrict__ enc, float* __restrict__ o) {
    int idx = blockIdx.x*256 + threadIdx.x;
    if (idx < Mn*384) {
        int r = idx / 384, c = idx - r*384;
        o[idx] = enc[(size_t)r*Dn + c];
    }
}
__global__ void copy_full(const float* __restrict__ s, float* __restrict__ d2, int n) {
    int i = blockIdx.x*256 + threadIdx.x;
    if (i < n) d2[i] = s[i];
}

// ---------------- launcher ----------------
extern "C" void kernel_launch(void* const* d_in, const int* in_sizes, int n_in,
                              void* d_out, int out_size)
{
    const float* x     = (const float*)d_in[0];
    const float* embk  = (const float*)d_in[1];
    const float* Wq    = (const float*)d_in[2];
    const float* bq    = (const float*)d_in[3];
    const float* Wk    = (const float*)d_in[4];
    const float* bk    = (const float*)d_in[5];
    const float* Wv    = (const float*)d_in[6];
    const float* bv    = (const float*)d_in[7];
    // d_in[8], d_in[9]: Wsig/bsig — dead code in reference (prior is deleted), skipped
    const float* Wo    = (const float*)d_in[10];
    const float* bo    = (const float*)d_in[11];
    const float* W1    = (const float*)d_in[12];
    const float* b1    = (const float*)d_in[13];
    const float* W2    = (const float*)d_in[14];
    const float* b2    = (const float*)d_in[15];
    const float* n1g   = (const float*)d_in[16];
    const float* n1b   = (const float*)d_in[17];
    const float* n2g   = (const float*)d_in[18];
    const float* n2b   = (const float*)d_in[19];
    const float* nfg   = (const float*)d_in[20];
    const float* nfb   = (const float*)d_in[21];
    const float* Wproj = (const float*)d_in[22];
    const float* bproj = (const float*)d_in[23];
    const float* Wfea  = (const float*)d_in[24];
    const float* bfea  = (const float*)d_in[25];
    float* out = (float*)d_out;

    float *emb,*h,*q,*k,*v,*attnv,*tmp,*x1,*enc,*ff1,*scores,*xcat,*kpadT;
    cudaGetSymbolAddress((void**)&emb,    g_emb);
    cudaGetSymbolAddress((void**)&h,      g_h);
    cudaGetSymbolAddress((void**)&q,      g_q);
    cudaGetSymbolAddress((void**)&k,      g_k);
    cudaGetSymbolAddress((void**)&v,      g_v);
    cudaGetSymbolAddress((void**)&attnv,  g_attnv);
    cudaGetSymbolAddress((void**)&tmp,    g_tmp);
    cudaGetSymbolAddress((void**)&x1,     g_x1);
    cudaGetSymbolAddress((void**)&enc,    g_enc);
    cudaGetSymbolAddress((void**)&ff1,    g_ff1);
    cudaGetSymbolAddress((void**)&scores, g_scores);
    cudaGetSymbolAddress((void**)&xcat,   g_xcat);
    cudaGetSymbolAddress((void**)&kpadT,  g_kpadT);

    // conv1d (wrap pad) as GEMM
    pack_kpadT<<<128, 512>>>(embk, kpadT);
    pack_xcat <<<Mn, 128>>>(x, xcat);
    gemm128<<<dim3(4, 64), 256>>>(xcat, 128, kpadT, Dn, nullptr, emb, Dn, 128, 0);

    for (int l = 0; l < NLn; l++) {
        const float* hin = (l == 0) ? emb : h;
        const size_t wO = (size_t)l*Dn*Dn;
        gemm128<<<dim3(4, 64), 256>>>(hin, Dn, Wq + wO, Dn, bq + l*Dn, q, Dn, Dn, 0);
        gemm128<<<dim3(4, 64), 256>>>(hin, Dn, Wk + wO, Dn, bk + l*Dn, k, Dn, Dn, 0);
        gemm128<<<dim3(4, 64), 256>>>(hin, Dn, Wv + wO, Dn, bv + l*Dn, v, Dn, Dn, 0);
        attn_scores<<<dim3(8, 8, BHn), 256>>>(q, k, scores);
        softmax512<<<BHn*Ln, 256>>>(scores);
        attn_out<<<dim3(1, 8, BHn), 256>>>(scores, v, attnv);
        gemm128<<<dim3(4, 64), 256>>>(attnv, Dn, Wo + wO, Dn, bo + l*Dn, tmp, Dn, Dn, 0);
        add_ln512<<<Mn, 256>>>(hin, tmp, n1g + l*Dn, n1b + l*Dn, x1);
        gemm128<<<dim3(16, 64), 256>>>(x1, Dn, W1 + (size_t)l*Dn*DFFn, DFFn,
                                       b1 + l*DFFn, ff1, DFFn, Dn, 1 /*gelu*/);
        gemm128<<<dim3(4, 64), 256>>>(ff1, DFFn, W2 + (size_t)l*DFFn*Dn, Dn,
                                      b2 + l*Dn, tmp, Dn, DFFn, 0);
        add_ln512<<<Mn, 256>>>(x1, tmp, n2g + l*Dn, n2b + l*Dn, h);
    }

    add_ln512<<<Mn, 256>>>(h, nullptr, nfg, nfb, enc);

    // outputs: fea_t | enc_res | rec_temp | emb
    const size_t OFF_FEA = 0;
    const size_t OFF_RES = (size_t)Mn*Dn;                 //  4,194,304
    const size_t OFF_REC = OFF_RES + (size_t)Mn*384;      //  7,340,032
    const size_t OFF_EMB = OFF_REC + (size_t)Mn*Dn;       // 11,534,336

    gemm128<<<dim3(4, 64), 256>>>(enc + (Dn - DRESn), Dn, Wfea, Dn, bfea,
                                  out + OFF_FEA, Dn, DRESn, 0);
    copy_res<<<(Mn*384 + 255)/256, 256>>>(enc, out + OFF_RES);
    gemm128<<<dim3(4, 64), 256>>>(enc, Dn, Wproj, Dn, bproj,
                                  out + OFF_REC, Dn, Dn, 0);
    copy_full<<<(Mn*Dn + 255)/256, 256>>>(emb, out + OFF_EMB, Mn*Dn);
}

// round 3
// speedup vs baseline: 2.4051x; 2.4051x over previous
#include <cuda_runtime.h>
#include <cuda.h>
#include <math.h>

#define Bn   16
#define Ln   512
#define Cn   38
#define Dn   512
#define Hn   8
#define En   64
#define DFFn 2048
#define NLn  3
#define DRESn 128
#define Mn   (Bn*Ln)     /* 8192 */
#define BHn  (Bn*Hn)     /* 128  */

// ---------------- scratch (static device memory) ----------------
__device__ float g_emb  [Mn*Dn];
__device__ float g_h    [Mn*Dn];
__device__ float g_q    [Mn*Dn];
__device__ float g_k    [Mn*Dn];
__device__ float g_v    [Mn*Dn];
__device__ float g_attnv[Mn*Dn];
__device__ float g_tmp  [Mn*Dn];
__device__ float g_x1   [Mn*Dn];
__device__ float g_enc  [Mn*Dn];
__device__ float g_ff1  [Mn*DFFn];
__device__ float g_scores[33554432];         // 128*512*512
__device__ float g_xcat [Mn*128];
__device__ float g_vt   [BHn*En*Ln];         // [z][e][s]
__device__ float g_wt   [9830400];           // transposed weights

#define WTQ 0
#define WTK 786432
#define WTV 1572864
#define WTO 2359296
#define WT1 3145728
#define WT2 6291456
#define WTP 9437184
#define WTF 9699328
#define KTF 9764864

// ================= helpers =================
__device__ __forceinline__ unsigned smem_u32(const void* p) {
    unsigned a;
    asm("{ .reg .u64 t; cvta.to.shared.u64 t, %1; cvt.u32.u64 %0, t; }"
        : "=r"(a) : "l"(p));
    return a;
}
__device__ __forceinline__ unsigned cvt_tf32(float f) {
    unsigned u; asm("cvt.rna.tf32.f32 %0, %1;" : "=r"(u) : "f"(f)); return u;
}
__device__ __forceinline__ void mma8(float* c, const unsigned* a, const unsigned* b) {
    asm volatile("mma.sync.aligned.m16n8k8.row.col.f32.tf32.tf32.f32 "
        "{%0,%1,%2,%3}, {%4,%5,%6,%7}, {%8,%9}, {%0,%1,%2,%3};"
        : "+f"(c[0]), "+f"(c[1]), "+f"(c[2]), "+f"(c[3])
        : "r"(a[0]), "r"(a[1]), "r"(a[2]), "r"(a[3]), "r"(b[0]), "r"(b[1]));
}
#define CP16(sa, gp) \
    asm volatile("cp.async.cg.shared.global [%0], [%1], 16;" :: "r"(sa), "l"(gp))
#define CPCOMMIT() asm volatile("cp.async.commit_group;" ::: "memory")
#define CPWAIT(n)  asm volatile("cp.async.wait_group %0;" :: "n"(n) : "memory")

// ================= tensor-core GEMM via mma.sync (tf32) =================
// C[128 x NT] per CTA: C = A[M,K] @ BT[N,K]^T  (BT stored [N][K] row-major)
// MODE 0: plain    MODE 1: attention scores batch    MODE 2: attn*V batch
template<int NT, int MODE>
__global__ __launch_bounds__(256, 2)
void gemm_mma(const float* __restrict__ A, int lda,
              const float* __restrict__ BT, int ldb,
              const float* __restrict__ bias,
              float* __restrict__ C, int ldc,
              int K, float scale, int do_gelu)
{
    constexpr int WC  = (NT == 128) ? 4 : 2;   // warp cols (n), each 32 wide
    constexpr int WM  = (NT == 128) ? 64 : 32; // warp tile m
    constexpr int MT  = WM / 16;               // m16 tiles per warp
    constexpr int ASZ = 128 * 36;              // floats (pad 4)
    constexpr int BSZ = NT * 36;
    constexpr int STG = ASZ + BSZ;

    extern __shared__ float sm[];
    const int tid = threadIdx.x, w = tid >> 5, lane = tid & 31;
    const int m0 = blockIdx.y * 128, n0 = blockIdx.x * NT;

    size_t aoff = 0, boff = 0, coff = 0;
    if (MODE == 1) {
        int z = blockIdx.z;
        aoff = boff = ((size_t)(z >> 3) * Ln) * Dn + (size_t)(z & 7) * En;
        coff = (size_t)z * Ln * Ln;
    } else if (MODE == 2) {
        int z = blockIdx.z;
        aoff = (size_t)z * Ln * Ln;
        boff = (size_t)z * En * Ln;
        coff = ((size_t)(z >> 3) * Ln) * Dn + (size_t)(z & 7) * En;
    }
    const float* Ag = A + aoff;
    const float* Bg = BT + boff;

    auto load_stage = [&](int kc, int st) {
        float* As = sm + st * STG;
        float* Bs = As + ASZ;
        const float* Ap = Ag + (size_t)m0 * lda + kc * 32;
#pragma unroll
        for (int i = 0; i < 4; i++) {
            int fi = tid + i * 256, row = fi >> 3, seg = fi & 7;
            CP16(smem_u32(As + row * 36 + seg * 4), Ap + (size_t)row * lda + seg * 4);
        }
        const float* Bp = Bg + (size_t)n0 * ldb + kc * 32;
#pragma unroll
        for (int i = 0; i < NT / 32; i++) {
            int fi = tid + i * 256, row = fi >> 3, seg = fi & 7;
            CP16(smem_u32(Bs + row * 36 + seg * 4), Bp + (size_t)row * ldb + seg * 4);
        }
    };

    float acc[MT][4][4];
#pragma unroll
    for (int mt = 0; mt < MT; mt++)
#pragma unroll
        for (int nt = 0; nt < 4; nt++)
#pragma unroll
            for (int j = 0; j < 4; j++) acc[mt][nt][j] = 0.f;

    const int wm0 = (w / WC) * WM, wn0 = (w % WC) * 32;
    const int r = lane >> 2, cl = lane & 3;

    auto compute = [&](int st) {
        const float* As = sm + st * STG;
        const float* Bs = As + ASZ;
#pragma unroll
        for (int kk = 0; kk < 4; kk++) {
            const int kb = kk * 8;
            unsigned a[MT][4], b[4][2];
#pragma unroll
            for (int mt = 0; mt < MT; mt++) {
                const float* ap = As + (wm0 + mt * 16 + r) * 36 + kb + cl;
                a[mt][0] = cvt_tf32(ap[0]);
                a[mt][1] = cvt_tf32(ap[8 * 36]);
                a[mt][2] = cvt_tf32(ap[4]);
                a[mt][3] = cvt_tf32(ap[8 * 36 + 4]);
            }
#pragma unroll
            for (int nt = 0; nt < 4; nt++) {
                const float* bp = Bs + (wn0 + nt * 8 + r) * 36 + kb + cl;
                b[nt][0] = cvt_tf32(bp[0]);
                b[nt][1] = cvt_tf32(bp[4]);
            }
#pragma unroll
            for (int mt = 0; mt < MT; mt++)
#pragma unroll
                for (int nt = 0; nt < 4; nt++)
                    mma8(acc[mt][nt], a[mt], b[nt]);
        }
    };

    const int NC = K >> 5;
    load_stage(0, 0);
    CPCOMMIT();
    for (int c = 0; c < NC; c++) {
        if (c + 1 < NC) { load_stage(c + 1, (c + 1) & 1); CPCOMMIT(); CPWAIT(1); }
        else            { CPWAIT(0); }
        __syncthreads();
        compute(c & 1);
        __syncthreads();
    }

    // ---- epilogue ----
#pragma unroll
    for (int mt = 0; mt < MT; mt++) {
#pragma unroll
        for (int nt = 0; nt < 4; nt++) {
            int row = m0 + wm0 + mt * 16 + r;
            int col = n0 + wn0 + nt * 8 + cl * 2;
            float bs0 = bias ? bias[col] : 0.f;
            float bs1 = bias ? bias[col + 1] : 0.f;
            float v0 = acc[mt][nt][0] * scale + bs0;
            float v1 = acc[mt][nt][1] * scale + bs1;
            float v2 = acc[mt][nt][2] * scale + bs0;
            float v3 = acc[mt][nt][3] * scale + bs1;
            if (do_gelu) {
                v0 = 0.5f * v0 * (1.0f + erff(v0 * 0.70710678118654752f));
                v1 = 0.5f * v1 * (1.0f + erff(v1 * 0.70710678118654752f));
                v2 = 0.5f * v2 * (1.0f + erff(v2 * 0.70710678118654752f));
                v3 = 0.5f * v3 * (1.0f + erff(v3 * 0.70710678118654752f));
            }
            float* p0 = C + coff + (size_t)row * ldc + col;
            float* p1 = p0 + (size_t)8 * ldc;
            p0[0] = v0; p0[1] = v1;
            p1[0] = v2; p1[1] = v3;
        }
    }
}

// ================= packing / transpose =================
__global__ void pack_xcat(const float* __restrict__ x, float* __restrict__ xc) {
    int bl = blockIdx.x;
    int b = bl >> 9, l = bl & 511;
    int i = threadIdx.x;
    float val = 0.f;
    if (i < Cn * 3) {
        int c = i / 3, t = i - c * 3;
        int ls = (l - 1 + t + Ln) & (Ln - 1);
        val = x[((size_t)b * Ln + ls) * Cn + c];
    }
    xc[(size_t)bl * 128 + i] = val;
}
__global__ void pack_ktf(const float* __restrict__ kern, float* __restrict__ kt) {
    int d = blockIdx.x, i = threadIdx.x;
    kt[(size_t)d * 128 + i] = (i < Cn * 3) ? kern[(size_t)d * (Cn * 3) + i] : 0.f;
}
__global__ void transpose_kn(const float* __restrict__ in, float* __restrict__ out,
                             int K, int N) {
    __shared__ float t[32][33];
    int k0 = blockIdx.y * 32, n0 = blockIdx.x * 32;
    int tx = threadIdx.x, ty = threadIdx.y;
#pragma unroll
    for (int r = 0; r < 4; r++)
        t[ty + r * 8][tx] = in[(size_t)(k0 + ty + r * 8) * N + n0 + tx];
    __syncthreads();
#pragma unroll
    for (int r = 0; r < 4; r++)
        out[(size_t)(n0 + ty + r * 8) * K + k0 + tx] = t[tx][ty + r * 8];
}
__global__ void transpose_v(const float* __restrict__ v, float* __restrict__ vt) {
    __shared__ float t[64][65];
    int z = blockIdx.y, s0 = blockIdx.x * 64;
    int b = z >> 3, h = z & 7;
    const float* src = v + ((size_t)b * Ln) * Dn + (size_t)h * En;
    int e = threadIdx.x & 63, idx = threadIdx.x >> 6;
#pragma unroll
    for (int r = 0; r < 16; r++)
        t[idx + r * 4][e] = src[(size_t)(s0 + idx + r * 4) * Dn + e];
    __syncthreads();
    float* dst = vt + (size_t)z * En * Ln;
#pragma unroll
    for (int r = 0; r < 16; r++)
        dst[(size_t)(idx + r * 4) * Ln + s0 + e] = t[e][idx + r * 4];
}

// ================= softmax / layernorm / copies =================
__global__ void softmax512(float* __restrict__ s) {
    size_t row = blockIdx.x;
    float* p = s + row * 512;
    int t = threadIdx.x;
    float a = p[t], b = p[t + 256];
    float m = fmaxf(a, b);
#pragma unroll
    for (int o = 16; o > 0; o >>= 1) m = fmaxf(m, __shfl_xor_sync(0xFFFFFFFFu, m, o));
    __shared__ float sm[8], ss[8];
    if ((t & 31) == 0) sm[t >> 5] = m;
    __syncthreads();
    float M = fmaxf(fmaxf(fmaxf(sm[0], sm[1]), fmaxf(sm[2], sm[3])),
                    fmaxf(fmaxf(sm[4], sm[5]), fmaxf(sm[6], sm[7])));
    float e0 = __expf(a - M), e1 = __expf(b - M);
    float su = e0 + e1;
#pragma unroll
    for (int o = 16; o > 0; o >>= 1) su += __shfl_xor_sync(0xFFFFFFFFu, su, o);
    if ((t & 31) == 0) ss[t >> 5] = su;
    __syncthreads();
    float S = ss[0] + ss[1] + ss[2] + ss[3] + ss[4] + ss[5] + ss[6] + ss[7];
    float inv = 1.0f / S;
    p[t] = e0 * inv;
    p[t + 256] = e1 * inv;
}
__global__ void add_ln512(const float* __restrict__ a, const float* __restrict__ b,
                          const float* __restrict__ g, const float* __restrict__ be,
                          float* __restrict__ o) {
    int row = blockIdx.x, t = threadIdx.x;
    size_t base = (size_t)row * Dn;
    float v0 = a[base + t], v1 = a[base + t + 256];
    if (b) { v0 += b[base + t]; v1 += b[base + t + 256]; }
    float s = v0 + v1;
#pragma unroll
    for (int oo = 16; oo > 0; oo >>= 1) s += __shfl_xor_sync(0xFFFFFFFFu, s, oo);
    __shared__ float s1[8], s2[8];
    if ((t & 31) == 0) s1[t >> 5] = s;
    __syncthreads();
    float mean = (s1[0] + s1[1] + s1[2] + s1[3] + s1[4] + s1[5] + s1[6] + s1[7]) * (1.0f / Dn);
    float d0 = v0 - mean, d1 = v1 - mean;
    float q2 = d0 * d0 + d1 * d1;
#pragma unroll
    for (int oo = 16; oo > 0; oo >>= 1) q2 += __shfl_xor_sync(0xFFFFFFFFu, q2, oo);
    if ((t & 31) == 0) s2[t >> 5] = q2;
    __syncthreads();
    float var = (s2[0] + s2[1] + s2[2] + s2[3] + s2[4] + s2[5] + s2[6] + s2[7]) * (1.0f / Dn);
    float r = rsqrtf(var + 1e-5f);
    o[base + t]       = d0 * r * g[t]       + be[t];
    o[base + t + 256] = d1 * r * g[t + 256] + be[t + 256];
}
__global__ void copy_res(const float* __restrict__ enc, float* __restrict__ o) {
    int idx = blockIdx.x * 256 + threadIdx.x;
    if (idx < Mn * 384) {
        int r = idx / 384, c = idx - r * 384;
        o[idx] = enc[(size_t)r * Dn + c];
    }
}
__global__ void copy_full(const float* __restrict__ s, float* __restrict__ d2, int n) {
    int i = blockIdx.x * 256 + threadIdx.x;
    if (i < n) d2[i] = s[i];
}

// ================= launcher =================
extern "C" void kernel_launch(void* const* d_in, const int* in_sizes, int n_in,
                              void* d_out, int out_size)
{
    const float* x     = (const float*)d_in[0];
    const float* embk  = (const float*)d_in[1];
    const float* Wq    = (const float*)d_in[2];
    const float* bq    = (const float*)d_in[3];
    const float* Wk    = (const float*)d_in[4];
    const float* bk    = (const float*)d_in[5];
    const float* Wv    = (const float*)d_in[6];
    const float* bv    = (const float*)d_in[7];
    // d_in[8], d_in[9]: Wsig/bsig are dead code in the reference
    const float* Wo    = (const float*)d_in[10];
    const float* bo    = (const float*)d_in[11];
    const float* W1    = (const float*)d_in[12];
    const float* b1    = (const float*)d_in[13];
    const float* W2    = (const float*)d_in[14];
    const float* b2    = (const float*)d_in[15];
    const float* n1g   = (const float*)d_in[16];
    const float* n1b   = (const float*)d_in[17];
    const float* n2g   = (const float*)d_in[18];
    const float* n2b   = (const float*)d_in[19];
    const float* nfg   = (const float*)d_in[20];
    const float* nfb   = (const float*)d_in[21];
    const float* Wproj = (const float*)d_in[22];
    const float* bproj = (const float*)d_in[23];
    const float* Wfea  = (const float*)d_in[24];
    const float* bfea  = (const float*)d_in[25];
    float* out = (float*)d_out;

    float *emb,*h,*q,*k,*v,*attnv,*tmp,*x1,*enc,*ff1,*scores,*xcat,*vt,*wt;
    cudaGetSymbolAddress((void**)&emb,    g_emb);
    cudaGetSymbolAddress((void**)&h,      g_h);
    cudaGetSymbolAddress((void**)&q,      g_q);
    cudaGetSymbolAddress((void**)&k,      g_k);
    cudaGetSymbolAddress((void**)&v,      g_v);
    cudaGetSymbolAddress((void**)&attnv,  g_attnv);
    cudaGetSymbolAddress((void**)&tmp,    g_tmp);
    cudaGetSymbolAddress((void**)&x1,     g_x1);
    cudaGetSymbolAddress((void**)&enc,    g_enc);
    cudaGetSymbolAddress((void**)&ff1,    g_ff1);
    cudaGetSymbolAddress((void**)&scores, g_scores);
    cudaGetSymbolAddress((void**)&xcat,   g_xcat);
    cudaGetSymbolAddress((void**)&vt,     g_vt);
    cudaGetSymbolAddress((void**)&wt,     g_wt);

    const int SM128 = (128 + 128) * 36 * 4 * 2;   // 73728
    const int SM64  = (128 +  64) * 36 * 4 * 2;   // 55296
    cudaFuncSetAttribute((const void*)gemm_mma<128,0>, cudaFuncAttributeMaxDynamicSharedMemorySize, SM128);
    cudaFuncSetAttribute((const void*)gemm_mma<128,1>, cudaFuncAttributeMaxDynamicSharedMemorySize, SM128);
    cudaFuncSetAttribute((const void*)gemm_mma<64,2>,  cudaFuncAttributeMaxDynamicSharedMemorySize, SM64);

    // ---- per-launch weight transposes + packs ----
    pack_ktf<<<512, 128>>>(embk, wt + KTF);
    pack_xcat<<<Mn, 128>>>(x, xcat);
    dim3 tb(32, 8);
    for (int l = 0; l < NLn; l++) {
        size_t o512 = (size_t)l * Dn * Dn, o1 = (size_t)l * Dn * DFFn;
        transpose_kn<<<dim3(16, 16), tb>>>(Wq + o512, wt + WTQ + o512, Dn, Dn);
        transpose_kn<<<dim3(16, 16), tb>>>(Wk + o512, wt + WTK + o512, Dn, Dn);
        transpose_kn<<<dim3(16, 16), tb>>>(Wv + o512, wt + WTV + o512, Dn, Dn);
        transpose_kn<<<dim3(16, 16), tb>>>(Wo + o512, wt + WTO + o512, Dn, Dn);
        transpose_kn<<<dim3(64, 16), tb>>>(W1 + o1,   wt + WT1 + o1,   Dn, DFFn);
        transpose_kn<<<dim3(16, 64), tb>>>(W2 + o1,   wt + WT2 + o1,   DFFn, Dn);
    }
    transpose_kn<<<dim3(16, 16), tb>>>(Wproj, wt + WTP, Dn, Dn);
    transpose_kn<<<dim3(16, 4),  tb>>>(Wfea,  wt + WTF, DRESn, Dn);

    // conv1d as GEMM
    gemm_mma<128,0><<<dim3(4, 64), 256, SM128>>>(xcat, 128, wt + KTF, 128, nullptr,
                                                 emb, Dn, 128, 1.0f, 0);

    for (int l = 0; l < NLn; l++) {
        const float* hin = (l == 0) ? emb : h;
        size_t o512 = (size_t)l * Dn * Dn, o1 = (size_t)l * Dn * DFFn;
        gemm_mma<128,0><<<dim3(4, 64), 256, SM128>>>(hin, Dn, wt + WTQ + o512, Dn,
                                                     bq + l * Dn, q, Dn, Dn, 1.0f, 0);
        gemm_mma<128,0><<<dim3(4, 64), 256, SM128>>>(hin, Dn, wt + WTK + o512, Dn,
                                                     bk + l * Dn, k, Dn, Dn, 1.0f, 0);
        gemm_mma<128,0><<<dim3(4, 64), 256, SM128>>>(hin, Dn, wt + WTV + o512, Dn,
                                                     bv + l * Dn, v, Dn, Dn, 1.0f, 0);
        transpose_v<<<dim3(8, BHn), 256>>>(v, vt);
        gemm_mma<128,1><<<dim3(4, 4, BHn), 256, SM128>>>(q, Dn, k, Dn, nullptr,
                                                         scores, Ln, En, 0.125f, 0);
        softmax512<<<BHn * Ln, 256>>>(scores);
        gemm_mma<64,2><<<dim3(1, 4, BHn), 256, SM64>>>(scores, Ln, vt, Ln, nullptr,
                                                       attnv, Dn, Ln, 1.0f, 0);
        gemm_mma<128,0><<<dim3(4, 64), 256, SM128>>>(attnv, Dn, wt + WTO + o512, Dn,
                                                     bo + l * Dn, tmp, Dn, Dn, 1.0f, 0);
        add_ln512<<<Mn, 256>>>(hin, tmp, n1g + l * Dn, n1b + l * Dn, x1);
        gemm_mma<128,0><<<dim3(16, 64), 256, SM128>>>(x1, Dn, wt + WT1 + o1, Dn,
                                                      b1 + l * DFFn, ff1, DFFn, Dn, 1.0f, 1);
        gemm_mma<128,0><<<dim3(4, 64), 256, SM128>>>(ff1, DFFn, wt + WT2 + o1, DFFn,
                                                     b2 + l * Dn, tmp, Dn, DFFn, 1.0f, 0);
        add_ln512<<<Mn, 256>>>(x1, tmp, n2g + l * Dn, n2b + l * Dn, h);
    }

    add_ln512<<<Mn, 256>>>(h, nullptr, nfg, nfb, enc);

    // outputs: fea_t | enc_res | rec_temp | emb
    const size_t OFF_FEA = 0;
    const size_t OFF_RES = (size_t)Mn * Dn;
    const size_t OFF_REC = OFF_RES + (size_t)Mn * 384;
    const size_t OFF_EMB = OFF_REC + (size_t)Mn * Dn;

    gemm_mma<128,0><<<dim3(4, 64), 256, SM128>>>(enc + (Dn - DRESn), Dn, wt + WTF, DRESn,
                                                 bfea, out + OFF_FEA, Dn, DRESn, 1.0f, 0);
    copy_res<<<(Mn * 384 + 255) / 256, 256>>>(enc, out + OFF_RES);
    gemm_mma<128,0><<<dim3(4, 64), 256, SM128>>>(enc, Dn, wt + WTP, Dn,
                                                 bproj, out + OFF_REC, Dn, Dn, 1.0f, 0);
    copy_full<<<(Mn * Dn + 255) / 256, 256>>>(emb, out + OFF_EMB, Mn * Dn);
}

// round 4
// speedup vs baseline: 2.5318x; 1.0527x over previous
#include <cuda_runtime.h>
#include <cuda.h>
#include <math.h>

#define Bn   16
#define Ln   512
#define Cn   38
#define Dn   512
#define Hn   8
#define En   64
#define DFFn 2048
#define NLn  3
#define DRESn 128
#define Mn   (Bn*Ln)     /* 8192 */
#define BHn  (Bn*Hn)     /* 128  */

// ---------------- scratch (static device memory) ----------------
__device__ float g_h    [Mn*Dn];
__device__ float g_q    [Mn*Dn];
__device__ float g_k    [Mn*Dn];
__device__ float g_v    [Mn*Dn];
__device__ float g_attnv[Mn*Dn];
__device__ float g_tmp  [Mn*Dn];
__device__ float g_x1   [Mn*Dn];
__device__ float g_enc  [Mn*Dn];
__device__ float g_ff1  [Mn*DFFn];
__device__ float g_scores[33554432];         // 128*512*512
__device__ float g_xcat [Mn*128];
__device__ float g_vt   [BHn*En*Ln];         // [z][e][s]
__device__ float g_wt   [9830400];           // transposed weights

#define WTQ 0
#define WTK 786432
#define WTV 1572864
#define WTO 2359296
#define WT1 3145728
#define WT2 6291456
#define WTP 9437184
#define WTF 9699328
#define KTF 9764864

// ================= helpers =================
__device__ __forceinline__ unsigned smem_u32(const void* p) {
    unsigned a;
    asm("{ .reg .u64 t; cvta.to.shared.u64 t, %1; cvt.u32.u64 %0, t; }"
        : "=r"(a) : "l"(p));
    return a;
}
__device__ __forceinline__ unsigned cvt_tf32(float f) {
    unsigned u; asm("cvt.rna.tf32.f32 %0, %1;" : "=r"(u) : "f"(f)); return u;
}
__device__ __forceinline__ void mma8(float* c, const unsigned* a, const unsigned* b) {
    asm volatile("mma.sync.aligned.m16n8k8.row.col.f32.tf32.tf32.f32 "
        "{%0,%1,%2,%3}, {%4,%5,%6,%7}, {%8,%9}, {%0,%1,%2,%3};"
        : "+f"(c[0]), "+f"(c[1]), "+f"(c[2]), "+f"(c[3])
        : "r"(a[0]), "r"(a[1]), "r"(a[2]), "r"(a[3]), "r"(b[0]), "r"(b[1]));
}
#define CP16(sa, gp) \
    asm volatile("cp.async.cg.shared.global [%0], [%1], 16;" :: "r"(sa), "l"(gp))
#define CPCOMMIT() asm volatile("cp.async.commit_group;" ::: "memory")
#define CPWAIT(n)  asm volatile("cp.async.wait_group %0;" :: "n"(n) : "memory")

// ================= tensor-core GEMM via mma.sync (tf32) =================
// C[128 x NT] per CTA: C = A[M,K] @ BT[N,K]^T  (BT stored [N][K] row-major)
// MODE 0: plain    MODE 2: attn*V batch
template<int NT, int MODE>
__global__ __launch_bounds__(256, 2)
void gemm_mma(const float* __restrict__ A, int lda,
              const float* __restrict__ BT, int ldb,
              const float* __restrict__ bias,
              float* __restrict__ C, int ldc,
              int K, float scale, int do_gelu)
{
    constexpr int WC  = (NT == 128) ? 4 : 2;
    constexpr int WM  = (NT == 128) ? 64 : 32;
    constexpr int MT  = WM / 16;
    constexpr int ASZ = 128 * 36;
    constexpr int BSZ = NT * 36;
    constexpr int STG = ASZ + BSZ;

    extern __shared__ float sm[];
    const int tid = threadIdx.x, w = tid >> 5, lane = tid & 31;
    const int m0 = blockIdx.y * 128, n0 = blockIdx.x * NT;

    size_t aoff = 0, boff = 0, coff = 0;
    if (MODE == 2) {
        int z = blockIdx.z;
        aoff = (size_t)z * Ln * Ln;
        boff = (size_t)z * En * Ln;
        coff = ((size_t)(z >> 3) * Ln) * Dn + (size_t)(z & 7) * En;
    }
    const float* Ag = A + aoff;
    const float* Bg = BT + boff;

    auto load_stage = [&](int kc, int st) {
        float* As = sm + st * STG;
        float* Bs = As + ASZ;
        const float* Ap = Ag + (size_t)m0 * lda + kc * 32;
#pragma unroll
        for (int i = 0; i < 4; i++) {
            int fi = tid + i * 256, row = fi >> 3, seg = fi & 7;
            CP16(smem_u32(As + row * 36 + seg * 4), Ap + (size_t)row * lda + seg * 4);
        }
        const float* Bp = Bg + (size_t)n0 * ldb + kc * 32;
#pragma unroll
        for (int i = 0; i < NT / 32; i++) {
            int fi = tid + i * 256, row = fi >> 3, seg = fi & 7;
            CP16(smem_u32(Bs + row * 36 + seg * 4), Bp + (size_t)row * ldb + seg * 4);
        }
    };

    float acc[MT][4][4];
#pragma unroll
    for (int mt = 0; mt < MT; mt++)
#pragma unroll
        for (int nt = 0; nt < 4; nt++)
#pragma unroll
            for (int j = 0; j < 4; j++) acc[mt][nt][j] = 0.f;

    const int wm0 = (w / WC) * WM, wn0 = (w % WC) * 32;
    const int r = lane >> 2, cl = lane & 3;

    auto compute = [&](int st) {
        const float* As = sm + st * STG;
        const float* Bs = As + ASZ;
#pragma unroll
        for (int kk = 0; kk < 4; kk++) {
            const int kb = kk * 8;
            unsigned a[MT][4], b[4][2];
#pragma unroll
            for (int mt = 0; mt < MT; mt++) {
                const float* ap = As + (wm0 + mt * 16 + r) * 36 + kb + cl;
                a[mt][0] = cvt_tf32(ap[0]);
                a[mt][1] = cvt_tf32(ap[8 * 36]);
                a[mt][2] = cvt_tf32(ap[4]);
                a[mt][3] = cvt_tf32(ap[8 * 36 + 4]);
            }
#pragma unroll
            for (int nt = 0; nt < 4; nt++) {
                const float* bp = Bs + (wn0 + nt * 8 + r) * 36 + kb + cl;
                b[nt][0] = cvt_tf32(bp[0]);
                b[nt][1] = cvt_tf32(bp[4]);
            }
#pragma unroll
            for (int mt = 0; mt < MT; mt++)
#pragma unroll
                for (int nt = 0; nt < 4; nt++)
                    mma8(acc[mt][nt], a[mt], b[nt]);
        }
    };

    const int NC = K >> 5;
    load_stage(0, 0);
    CPCOMMIT();
    for (int c = 0; c < NC; c++) {
        if (c + 1 < NC) { load_stage(c + 1, (c + 1) & 1); CPCOMMIT(); CPWAIT(1); }
        else            { CPWAIT(0); }
        __syncthreads();
        compute(c & 1);
        __syncthreads();
    }

#pragma unroll
    for (int mt = 0; mt < MT; mt++) {
#pragma unroll
        for (int nt = 0; nt < 4; nt++) {
            int row = m0 + wm0 + mt * 16 + r;
            int col = n0 + wn0 + nt * 8 + cl * 2;
            float bs0 = bias ? bias[col] : 0.f;
            float bs1 = bias ? bias[col + 1] : 0.f;
            float v0 = acc[mt][nt][0] * scale + bs0;
            float v1 = acc[mt][nt][1] * scale + bs1;
            float v2 = acc[mt][nt][2] * scale + bs0;
            float v3 = acc[mt][nt][3] * scale + bs1;
            if (do_gelu) {
                v0 = 0.5f * v0 * (1.0f + erff(v0 * 0.70710678118654752f));
                v1 = 0.5f * v1 * (1.0f + erff(v1 * 0.70710678118654752f));
                v2 = 0.5f * v2 * (1.0f + erff(v2 * 0.70710678118654752f));
                v3 = 0.5f * v3 * (1.0f + erff(v3 * 0.70710678118654752f));
            }
            float* p0 = C + coff + (size_t)row * ldc + col;
            float* p1 = p0 + (size_t)8 * ldc;
            p0[0] = v0; p0[1] = v1;
            p1[0] = v2; p1[1] = v3;
        }
    }
}

// ================= fused scores + softmax =================
// grid (z=BHn, mtile=16); CTA 256 thr. Each CTA: P[32 x 512] for one (b,h),
// Q(32x64) + K(512x64) in smem (pre-cvt to tf32), row softmax in-register.
#define FS_QS   0
#define FS_KS   2176            /* 32*68 */
#define FS_RED  36992           /* 2176 + 512*68 */
#define FS_SMEM ((36992 + 512) * 4)

__global__ __launch_bounds__(256, 1)
void fused_scores_softmax(const float* __restrict__ q,
                          const float* __restrict__ kmat,
                          float* __restrict__ scores)
{
    extern __shared__ float sm[];
    const int tid = threadIdx.x, w = tid >> 5, lane = tid & 31;
    const int r = lane >> 2, cl = lane & 3;
    const int z = blockIdx.x;
    const int m0 = blockIdx.y * 32;
    const size_t off = ((size_t)(z >> 3) * Ln) * Dn + (size_t)(z & 7) * En;

    unsigned* Qs = (unsigned*)(sm + FS_QS);
    unsigned* Ks = (unsigned*)(sm + FS_KS);
    float* red  = sm + FS_RED;           // [8][32]
    float* red2 = red + 256;             // [8][32]

    // load Q (32x64) + K (512x64), convert to tf32 at store time
    {
        const float* Qp = q + off;
#pragma unroll
        for (int i = 0; i < 2; i++) {
            int idx = tid + i * 256, row = idx >> 4, seg = idx & 15;
            float4 v = *(const float4*)(Qp + (size_t)(m0 + row) * Dn + seg * 4);
            unsigned* d = Qs + row * 68 + seg * 4;
            d[0] = cvt_tf32(v.x); d[1] = cvt_tf32(v.y);
            d[2] = cvt_tf32(v.z); d[3] = cvt_tf32(v.w);
        }
        const float* Kp = kmat + off;
#pragma unroll 8
        for (int i = 0; i < 32; i++) {
            int idx = tid + i * 256, row = idx >> 4, seg = idx & 15;
            float4 v = *(const float4*)(Kp + (size_t)row * Dn + seg * 4);
            unsigned* d = Ks + row * 68 + seg * 4;
            d[0] = cvt_tf32(v.x); d[1] = cvt_tf32(v.y);
            d[2] = cvt_tf32(v.z); d[3] = cvt_tf32(v.w);
        }
    }
    __syncthreads();

    // compute 32x64 per warp: warp w owns cols [w*64, w*64+64)
    const int wn0 = w * 64;
    float acc[2][8][4];
#pragma unroll
    for (int mt = 0; mt < 2; mt++)
#pragma unroll
        for (int nt = 0; nt < 8; nt++)
#pragma unroll
            for (int j = 0; j < 4; j++) acc[mt][nt][j] = 0.f;

#pragma unroll
    for (int kk = 0; kk < 8; kk++) {
        const int kb = kk * 8;
        unsigned a[2][4], b[8][2];
#pragma unroll
        for (int mt = 0; mt < 2; mt++) {
            const unsigned* ap = Qs + (mt * 16 + r) * 68 + kb + cl;
            a[mt][0] = ap[0]; a[mt][1] = ap[8 * 68];
            a[mt][2] = ap[4]; a[mt][3] = ap[8 * 68 + 4];
        }
#pragma unroll
        for (int nt = 0; nt < 8; nt++) {
            const unsigned* bp = Ks + (wn0 + nt * 8 + r) * 68 + kb + cl;
            b[nt][0] = bp[0]; b[nt][1] = bp[4];
        }
#pragma unroll
        for (int mt = 0; mt < 2; mt++)
#pragma unroll
            for (int nt = 0; nt < 8; nt++)
                mma8(acc[mt][nt], a[mt], b[nt]);
    }

    // ---- row softmax over 512 cols (8 warps x 64) ----
    float M[4], inv[4];
#pragma unroll
    for (int rs = 0; rs < 4; rs++) {
        int mt = rs >> 1, jb = (rs & 1) * 2;
        float mx = -1e30f;
#pragma unroll
        for (int nt = 0; nt < 8; nt++)
            mx = fmaxf(mx, fmaxf(acc[mt][nt][jb], acc[mt][nt][jb + 1]));
        mx = fmaxf(mx, __shfl_xor_sync(0xFFFFFFFFu, mx, 1));
        mx = fmaxf(mx, __shfl_xor_sync(0xFFFFFFFFu, mx, 2));
        M[rs] = mx;
        if (cl == 0) red[w * 32 + mt * 16 + r + (rs & 1) * 8] = mx;
    }
    __syncthreads();
#pragma unroll
    for (int rs = 0; rs < 4; rs++) {
        int row = (rs >> 1) * 16 + r + (rs & 1) * 8;
        float mx = -1e30f;
#pragma unroll
        for (int w2 = 0; w2 < 8; w2++) mx = fmaxf(mx, red[w2 * 32 + row]);
        M[rs] = mx;
    }
#pragma unroll
    for (int rs = 0; rs < 4; rs++) {
        int mt = rs >> 1, jb = (rs & 1) * 2;
        float s = 0.f;
#pragma unroll
        for (int nt = 0; nt < 8; nt++) {
            float e0 = __expf((acc[mt][nt][jb]     - M[rs]) * 0.125f);
            float e1 = __expf((acc[mt][nt][jb + 1] - M[rs]) * 0.125f);
            acc[mt][nt][jb] = e0; acc[mt][nt][jb + 1] = e1;
            s += e0 + e1;
        }
        s += __shfl_xor_sync(0xFFFFFFFFu, s, 1);
        s += __shfl_xor_sync(0xFFFFFFFFu, s, 2);
        if (cl == 0) red2[w * 32 + mt * 16 + r + (rs & 1) * 8] = s;
    }
    __syncthreads();
#pragma unroll
    for (int rs = 0; rs < 4; rs++) {
        int row = (rs >> 1) * 16 + r + (rs & 1) * 8;
        float s = 0.f;
#pragma unroll
        for (int w2 = 0; w2 < 8; w2++) s += red2[w2 * 32 + row];
        inv[rs] = 1.0f / s;
    }

    float* C = scores + (size_t)z * Ln * Ln;
#pragma unroll
    for (int mt = 0; mt < 2; mt++) {
#pragma unroll
        for (int nt = 0; nt < 8; nt++) {
            int row = m0 + mt * 16 + r;
            int col = wn0 + nt * 8 + cl * 2;
            float* p0 = C + (size_t)row * Ln + col;
            float* p1 = p0 + (size_t)8 * Ln;
            p0[0] = acc[mt][nt][0] * inv[mt * 2];
            p0[1] = acc[mt][nt][1] * inv[mt * 2];
            p1[0] = acc[mt][nt][2] * inv[mt * 2 + 1];
            p1[1] = acc[mt][nt][3] * inv[mt * 2 + 1];
        }
    }
}

// ================= packing / transpose =================
__global__ void pack_xcat(const float* __restrict__ x, float* __restrict__ xc) {
    int bl = blockIdx.x;
    int b = bl >> 9, l = bl & 511;
    int i = threadIdx.x;
    float val = 0.f;
    if (i < Cn * 3) {
        int c = i / 3, t = i - c * 3;
        int ls = (l - 1 + t + Ln) & (Ln - 1);
        val = x[((size_t)b * Ln + ls) * Cn + c];
    }
    xc[(size_t)bl * 128 + i] = val;
}
__global__ void pack_ktf(const float* __restrict__ kern, float* __restrict__ kt) {
    int d = blockIdx.x, i = threadIdx.x;
    kt[(size_t)d * 128 + i] = (i < Cn * 3) ? kern[(size_t)d * (Cn * 3) + i] : 0.f;
}
__global__ void transpose_kn(const float* __restrict__ in, float* __restrict__ out,
                             int K, int N) {
    __shared__ float t[32][33];
    int k0 = blockIdx.y * 32, n0 = blockIdx.x * 32;
    int tx = threadIdx.x, ty = threadIdx.y;
#pragma unroll
    for (int r = 0; r < 4; r++)
        t[ty + r * 8][tx] = in[(size_t)(k0 + ty + r * 8) * N + n0 + tx];
    __syncthreads();
#pragma unroll
    for (int r = 0; r < 4; r++)
        out[(size_t)(n0 + ty + r * 8) * K + k0 + tx] = t[tx][ty + r * 8];
}
__global__ void transpose_v(const float* __restrict__ v, float* __restrict__ vt) {
    __shared__ float t[64][65];
    int z = blockIdx.y, s0 = blockIdx.x * 64;
    int b = z >> 3, h = z & 7;
    const float* src = v + ((size_t)b * Ln) * Dn + (size_t)h * En;
    int e = threadIdx.x & 63, idx = threadIdx.x >> 6;
#pragma unroll
    for (int r = 0; r < 16; r++)
        t[idx + r * 4][e] = src[(size_t)(s0 + idx + r * 4) * Dn + e];
    __syncthreads();
    float* dst = vt + (size_t)z * En * Ln;
#pragma unroll
    for (int r = 0; r < 16; r++)
        dst[(size_t)(idx + r * 4) * Ln + s0 + e] = t[e][idx + r * 4];
}

// ================= layernorm (+optional residual, +optional 384-col copy) ====
__global__ void add_ln512(const float* __restrict__ a, const float* __restrict__ b,
                          const float* __restrict__ g, const float* __restrict__ be,
                          float* __restrict__ o, float* __restrict__ res) {
    int row = blockIdx.x, t = threadIdx.x;
    size_t base = (size_t)row * Dn;
    float v0 = a[base + t], v1 = a[base + t + 256];
    if (b) { v0 += b[base + t]; v1 += b[base + t + 256]; }
    float s = v0 + v1;
#pragma unroll
    for (int oo = 16; oo > 0; oo >>= 1) s += __shfl_xor_sync(0xFFFFFFFFu, s, oo);
    __shared__ float s1[8], s2[8];
    if ((t & 31) == 0) s1[t >> 5] = s;
    __syncthreads();
    float mean = (s1[0] + s1[1] + s1[2] + s1[3] + s1[4] + s1[5] + s1[6] + s1[7]) * (1.0f / Dn);
    float d0 = v0 - mean, d1 = v1 - mean;
    float q2 = d0 * d0 + d1 * d1;
#pragma unroll
    for (int oo = 16; oo > 0; oo >>= 1) q2 += __shfl_xor_sync(0xFFFFFFFFu, q2, oo);
    if ((t & 31) == 0) s2[t >> 5] = q2;
    __syncthreads();
    float var = (s2[0] + s2[1] + s2[2] + s2[3] + s2[4] + s2[5] + s2[6] + s2[7]) * (1.0f / Dn);
    float rr = rsqrtf(var + 1e-5f);
    float o0 = d0 * rr * g[t]       + be[t];
    float o1 = d1 * rr * g[t + 256] + be[t + 256];
    o[base + t]       = o0;
    o[base + t + 256] = o1;
    if (res) {
        res[(size_t)row * 384 + t] = o0;
        if (t < 128) res[(size_t)row * 384 + t + 256] = o1;
    }
}

// ================= launcher =================
extern "C" void kernel_launch(void* const* d_in, const int* in_sizes, int n_in,
                              void* d_out, int out_size)
{
    const float* x     = (const float*)d_in[0];
    const float* embk  = (const float*)d_in[1];
    const float* Wq    = (const float*)d_in[2];
    const float* bq    = (const float*)d_in[3];
    const float* Wk    = (const float*)d_in[4];
    const float* bk    = (const float*)d_in[5];
    const float* Wv    = (const float*)d_in[6];
    const float* bv    = (const float*)d_in[7];
    // d_in[8], d_in[9]: Wsig/bsig are dead code in the reference
    const float* Wo    = (const float*)d_in[10];
    const float* bo    = (const float*)d_in[11];
    const float* W1    = (const float*)d_in[12];
    const float* b1    = (const float*)d_in[13];
    const float* W2    = (const float*)d_in[14];
    const float* b2    = (const float*)d_in[15];
    const float* n1g   = (const float*)d_in[16];
    const float* n1b   = (const float*)d_in[17];
    const float* n2g   = (const float*)d_in[18];
    const float* n2b   = (const float*)d_in[19];
    const float* nfg   = (const float*)d_in[20];
    const float* nfb   = (const float*)d_in[21];
    const float* Wproj = (const float*)d_in[22];
    const float* bproj = (const float*)d_in[23];
    const float* Wfea  = (const float*)d_in[24];
    const float* bfea  = (const float*)d_in[25];
    float* out = (float*)d_out;

    float *h,*q,*k,*v,*attnv,*tmp,*x1,*enc,*ff1,*scores,*xcat,*vt,*wt;
    cudaGetSymbolAddress((void**)&h,      g_h);
    cudaGetSymbolAddress((void**)&q,      g_q);
    cudaGetSymbolAddress((void**)&k,      g_k);
    cudaGetSymbolAddress((void**)&v,      g_v);
    cudaGetSymbolAddress((void**)&attnv,  g_attnv);
    cudaGetSymbolAddress((void**)&tmp,    g_tmp);
    cudaGetSymbolAddress((void**)&x1,     g_x1);
    cudaGetSymbolAddress((void**)&enc,    g_enc);
    cudaGetSymbolAddress((void**)&ff1,    g_ff1);
    cudaGetSymbolAddress((void**)&scores, g_scores);
    cudaGetSymbolAddress((void**)&xcat,   g_xcat);
    cudaGetSymbolAddress((void**)&vt,     g_vt);
    cudaGetSymbolAddress((void**)&wt,     g_wt);

    // outputs: fea_t | enc_res | rec_temp | emb
    const size_t OFF_FEA = 0;
    const size_t OFF_RES = (size_t)Mn * Dn;
    const size_t OFF_REC = OFF_RES + (size_t)Mn * 384;
    const size_t OFF_EMB = OFF_REC + (size_t)Mn * Dn;
    float* emb = out + OFF_EMB;            // conv writes emb straight to output

    const int SM128 = (128 + 128) * 36 * 4 * 2;   // 73728
    const int SM64  = (128 +  64) * 36 * 4 * 2;   // 55296
    cudaFuncSetAttribute((const void*)gemm_mma<128,0>, cudaFuncAttributeMaxDynamicSharedMemorySize, SM128);
    cudaFuncSetAttribute((const void*)gemm_mma<64,2>,  cudaFuncAttributeMaxDynamicSharedMemorySize, SM64);
    cudaFuncSetAttribute((const void*)fused_scores_softmax, cudaFuncAttributeMaxDynamicSharedMemorySize, FS_SMEM);

    // ---- per-launch weight transposes + packs ----
    pack_ktf<<<512, 128>>>(embk, wt + KTF);
    pack_xcat<<<Mn, 128>>>(x, xcat);
    dim3 tb(32, 8);
    for (int l = 0; l < NLn; l++) {
        size_t o512 = (size_t)l * Dn * Dn, o1 = (size_t)l * Dn * DFFn;
        transpose_kn<<<dim3(16, 16), tb>>>(Wq + o512, wt + WTQ + o512, Dn, Dn);
        transpose_kn<<<dim3(16, 16), tb>>>(Wk + o512, wt + WTK + o512, Dn, Dn);
        transpose_kn<<<dim3(16, 16), tb>>>(Wv + o512, wt + WTV + o512, Dn, Dn);
        transpose_kn<<<dim3(16, 16), tb>>>(Wo + o512, wt + WTO + o512, Dn, Dn);
        transpose_kn<<<dim3(64, 16), tb>>>(W1 + o1,   wt + WT1 + o1,   Dn, DFFn);
        transpose_kn<<<dim3(16, 64), tb>>>(W2 + o1,   wt + WT2 + o1,   DFFn, Dn);
    }
    transpose_kn<<<dim3(16, 16), tb>>>(Wproj, wt + WTP, Dn, Dn);
    transpose_kn<<<dim3(16, 4),  tb>>>(Wfea,  wt + WTF, DRESn, Dn);

    // conv1d as GEMM (writes emb output in-place)
    gemm_mma<128,0><<<dim3(4, 64), 256, SM128>>>(xcat, 128, wt + KTF, 128, nullptr,
                                                 emb, Dn, 128, 1.0f, 0);

    for (int l = 0; l < NLn; l++) {
        const float* hin = (l == 0) ? emb : h;
        size_t o512 = (size_t)l * Dn * Dn, o1 = (size_t)l * Dn * DFFn;
        gemm_mma<128,0><<<dim3(4, 64), 256, SM128>>>(hin, Dn, wt + WTQ + o512, Dn,
                                                     bq + l * Dn, q, Dn, Dn, 1.0f, 0);
        gemm_mma<128,0><<<dim3(4, 64), 256, SM128>>>(hin, Dn, wt + WTK + o512, Dn,
                                                     bk + l * Dn, k, Dn, Dn, 1.0f, 0);
        gemm_mma<128,0><<<dim3(4, 64), 256, SM128>>>(hin, Dn, wt + WTV + o512, Dn,
                                                     bv + l * Dn, v, Dn, Dn, 1.0f, 0);
        transpose_v<<<dim3(8, BHn), 256>>>(v, vt);
        fused_scores_softmax<<<dim3(BHn, 16), 256, FS_SMEM>>>(q, k, scores);
        gemm_mma<64,2><<<dim3(1, 4, BHn), 256, SM64>>>(scores, Ln, vt, Ln, nullptr,
                                                       attnv, Dn, Ln, 1.0f, 0);
        gemm_mma<128,0><<<dim3(4, 64), 256, SM128>>>(attnv, Dn, wt + WTO + o512, Dn,
                                                     bo + l * Dn, tmp, Dn, Dn, 1.0f, 0);
        add_ln512<<<Mn, 256>>>(hin, tmp, n1g + l * Dn, n1b + l * Dn, x1, nullptr);
        gemm_mma<128,0><<<dim3(16, 64), 256, SM128>>>(x1, Dn, wt + WT1 + o1, Dn,
                                                      b1 + l * DFFn, ff1, DFFn, Dn, 1.0f, 1);
        gemm_mma<128,0><<<dim3(4, 64), 256, SM128>>>(ff1, DFFn, wt + WT2 + o1, DFFn,
                                                     b2 + l * Dn, tmp, Dn, DFFn, 1.0f, 0);
        add_ln512<<<Mn, 256>>>(x1, tmp, n2g + l * Dn, n2b + l * Dn, h, nullptr);
    }

    // final LN also emits enc_res (first 384 cols) fused
    add_ln512<<<Mn, 256>>>(h, nullptr, nfg, nfb, enc, out + OFF_RES);

    gemm_mma<128,0><<<dim3(4, 64), 256, SM128>>>(enc + (Dn - DRESn), Dn, wt + WTF, DRESn,
                                                 bfea, out + OFF_FEA, Dn, DRESn, 1.0f, 0);
    gemm_mma<128,0><<<dim3(4, 64), 256, SM128>>>(enc, Dn, wt + WTP, Dn,
                                                 bproj, out + OFF_REC, Dn, Dn, 1.0f, 0);
}